// round 11
// baseline (speedup 1.0000x reference)
#include <cuda_runtime.h>
#include <cuda_bf16.h>
#include <cstdint>

#define DEPTH_DIM 256
#define CAP       16             // slots per pixel; P(Poisson(1.11) >= 16) ~ 1e-13
#define MAX_PIX   (1 << 19)      // up to 512K pixels

__device__ int   g_cnt[MAX_PIX];              // zero-init at load; self-reset each launch
__device__ uint4 g_bin[MAX_PIX * CAP];        // {pd, na2, W=2^(2048 na2), U=2^(-64 na2)}

__device__ __forceinline__ float ex2_fast(float x) {
    float y;
    asm("ex2.approx.ftz.f32 %0, %1;" : "=f"(y) : "f"(x));
    return y;
}

// ---------------------------------------------------------------------------
// K1: bin points by pixel. Precompute na2 = C / sigma^2 (C = -0.5*h^2*log2 e,
//     h = 6/255) plus recurrence constants W = 2^(2048*na2), U = 2^(-64*na2).
// ---------------------------------------------------------------------------
__global__ void bin_kernel(const int2* __restrict__ pos,
                           const int*  __restrict__ depth,
                           const float* __restrict__ conf,
                           const int*  __restrict__ pW, int npts) {
    int i = blockIdx.x * blockDim.x + threadIdx.x;
    if (i >= npts) return;
    int W = __ldg(pW);
    int2 uv = __ldg(&pos[i]);
    int lin = uv.y * W + uv.x;
    int slot = atomicAdd(&g_cnt[lin], 1);
    if (slot < CAP) {
        const float C = -0.5f * (6.0f / 255.0f) * (6.0f / 255.0f) * 1.4426950408889634f;
        float sigma = __ldg(&conf[i]);
        float na2 = C / (sigma * sigma);
        uint4 v;
        v.x = (unsigned)__ldg(&depth[i]);
        v.y = __float_as_uint(na2);
        v.z = __float_as_uint(ex2_fast(2048.0f * na2));
        v.w = __float_as_uint(ex2_fast(-64.0f * na2));
        g_bin[lin * CAP + slot] = v;
    }
}

// ---------------------------------------------------------------------------
// K2: fused accumulate + transposed write. R10 recurrence hot loop, but
//     512 threads per 32-pixel block -> 4 blocks x 512 = 2048 thr/SM (100% occ,
//     smem 4 x 42KB = 168KB <= 228KB; launch_bounds(512,4) pins regs <= 32).
//   Warp w (0..15) owns pixels 2w, 2w+1; lane L owns depths L + 32m.
//   Math: j_m = (L - pd) + 32m;  e_m = 2^(na2 j_m^2) via e*=v, v*=W;
//   g_m = e_m (d<=pd, k=j_m) or e_m*c_m (d>pd, k=j_m-1), c*=U.
//   Tile stride 33: column store and row read both conflict-free.
// ---------------------------------------------------------------------------
__global__ void __launch_bounds__(512, 4) fused_kernel(float* __restrict__ out, int HW) {
    __shared__ float tile[DEPTH_DIM][33];
    __shared__ uint4 spts[32][CAP];            // 8KB
    __shared__ int   scnt[32];

    int tid  = threadIdx.x;
    int lane = tid & 31;
    int w    = tid >> 5;                       // 0..15
    int pBase = blockIdx.x * 32;

    // stage counters (and reset them for the next graph replay)
    if (tid < 32) {
        int p = pBase + tid;
        int c = 0;
        if (p < HW) {
            c = min(g_cnt[p], CAP);
            g_cnt[p] = 0;
        }
        scnt[tid] = c;
    }
    // stage the block's contiguous 8KB slab region: 512 threads x 16B
    {
        const uint4* src = reinterpret_cast<const uint4*>(g_bin + (size_t)pBase * CAP);
        (&spts[0][0])[tid] = src[tid];         // 32*CAP = 512 uint4s exactly
    }
    __syncthreads();

    #pragma unroll
    for (int jj = 0; jj < 2; ++jj) {
        int pl = w * 2 + jj;                   // pixel-in-block 0..31
        int cnt = scnt[pl];
        float acc[8] = {0.f, 0.f, 0.f, 0.f, 0.f, 0.f, 0.f, 0.f};
        for (int t = 0; t < cnt; ++t) {
            uint4 pv = spts[pl][t];            // smem broadcast (16B)
            int   pd  = (int)pv.x;
            float na2 = __uint_as_float(pv.y);
            float Wc  = __uint_as_float(pv.z);
            float Uc  = __uint_as_float(pv.w);

            int   k0  = lane - pd;             // j for m=0
            float j0  = (float)k0;
            float e  = ex2_fast(na2 * j0 * j0);
            float vr = ex2_fast(na2 * fmaf(64.0f, j0, 1024.0f));
            float c  = ex2_fast(na2 * fmaf(-2.0f, j0, 1.0f));

            float g[8];
            float s = 0.0f;
            #pragma unroll
            for (int m = 0; m < 8; ++m) {
                float gm = (k0 + 32 * m > 0) ? e * c : e;   // d > pd ?
                g[m] = gm;
                s = fmaf(gm, gm, s);
                e *= vr;  vr *= Wc;  c *= Uc;
            }
            #pragma unroll
            for (int o = 16; o > 0; o >>= 1)
                s += __shfl_xor_sync(0xffffffffu, s, o);
            float inv = rsqrtf(s);             // s >= 1 (k=0 term), no eps clamp
            #pragma unroll
            for (int m = 0; m < 8; ++m)
                acc[m] = fmaf(g[m], inv, acc[m]);
        }
        // column pl: bank = (lane + pl) % 32 -> conflict-free
        #pragma unroll
        for (int m = 0; m < 8; ++m)
            tile[lane + 32 * m][pl] = acc[m];
    }
    __syncthreads();

    // coalesced output: 16 warps x 16 depth rows, 32 consecutive pixels each
    int p = pBase + lane;
    if (p < HW) {
        #pragma unroll
        for (int m = 0; m < 16; ++m) {
            int d = w + m * 16;
            out[(size_t)d * HW + p] = tile[d][lane];
        }
    }
}

// ---------------------------------------------------------------------------
// Launch
// ---------------------------------------------------------------------------
extern "C" void kernel_launch(void* const* d_in, const int* in_sizes, int n_in,
                              void* d_out, int out_size) {
    const int2*  pos   = (const int2*)d_in[0];   // [N,2] int32 (u=x, v=y)
    const int*   depth = (const int*)d_in[1];    // [N,1] int32
    const float* conf  = (const float*)d_in[2];  // [N,1] float32
    const int*   pW    = (const int*)d_in[4];    // feat_w scalar

    int npts = in_sizes[1];
    int HW   = out_size / DEPTH_DIM;

    bin_kernel<<<(npts + 255) / 256, 256>>>(pos, depth, conf, pW, npts);
    fused_kernel<<<(HW + 31) / 32, 512>>>((float*)d_out, HW);
}

// round 12
// speedup vs baseline: 1.1416x; 1.1416x over previous
#include <cuda_runtime.h>
#include <cuda_bf16.h>
#include <cstdint>

#define DEPTH_DIM 256
#define CAP       16             // slots per pixel; P(Poisson(1.11) >= 16) ~ 1e-13
#define MAX_PIX   (1 << 19)      // up to 512K pixels
#define BLK_PIX   64
#define THREADS   512

__device__ int   g_cnt[MAX_PIX];              // zero-init at load; self-reset each launch
__device__ uint2 g_bin[MAX_PIX * CAP];        // {depth, na2 bits}

__device__ __forceinline__ float ex2_fast(float x) {
    float y;
    asm("ex2.approx.ftz.f32 %0, %1;" : "=f"(y) : "f"(x));
    return y;
}

// ---------------------------------------------------------------------------
// K1: bin points by pixel; precompute na2 = C / sigma^2 so the hot loop has
//     no division.  (C = -0.5 * h^2 * log2(e), h = 6/255)
// ---------------------------------------------------------------------------
__global__ void bin_kernel(const int2* __restrict__ pos,
                           const int*  __restrict__ depth,
                           const float* __restrict__ conf,
                           const int*  __restrict__ pW, int npts) {
    int i = blockIdx.x * blockDim.x + threadIdx.x;
    if (i >= npts) return;
    int W = __ldg(pW);
    int2 uv = __ldg(&pos[i]);
    int lin = uv.y * W + uv.x;
    int slot = atomicAdd(&g_cnt[lin], 1);
    if (slot < CAP) {
        const float C = -0.5f * (6.0f / 255.0f) * (6.0f / 255.0f) * 1.4426950408889634f;
        float sigma = __ldg(&conf[i]);
        uint2 v;
        v.x = (unsigned)__ldg(&depth[i]);
        v.y = __float_as_uint(C / (sigma * sigma));
        g_bin[lin * CAP + slot] = v;
    }
}

// ---------------------------------------------------------------------------
// K2: fused accumulate + transposed write. R6 hot loop; block = 64 pixels so
//     each depth-row write is 256B contiguous (vs 128B), streaming stores.
//   smem (dynamic, ~75KB): tile[256][65] f32 + spts[64][CAP] uint2 + scnt[64].
//   16 warps; warp w owns pixels 4w..4w+3 (jj loop, acc[8] per jj -> low regs).
//   Tile: column store banks (lane*65 + pl) % 32 = (lane+pl)%32 conflict-free;
//   row read consecutive. Counters staged + reset (zero at entry/exit).
// ---------------------------------------------------------------------------
__global__ void __launch_bounds__(THREADS, 3)
fused_kernel(float* __restrict__ out, int HW) {
    extern __shared__ char smem_raw[];
    float (*tile)[65]     = reinterpret_cast<float (*)[65]>(smem_raw);          // 66560B
    uint2 (*spts)[CAP]    = reinterpret_cast<uint2 (*)[CAP]>(smem_raw + 66560); // 8192B
    int*  scnt            = reinterpret_cast<int*>(smem_raw + 66560 + 8192);    // 256B

    int tid  = threadIdx.x;
    int lane = tid & 31;
    int w    = tid >> 5;                       // 0..15
    int pBase = blockIdx.x * BLK_PIX;

    // stage counters (and reset them for the next graph replay)
    if (tid < BLK_PIX) {
        int p = pBase + tid;
        int c = 0;
        if (p < HW) {
            c = min(g_cnt[p], CAP);
            g_cnt[p] = 0;
        }
        scnt[tid] = c;
    }
    // stage the block's contiguous 8KB slab region: 512 threads x 16B
    {
        const uint4* src = reinterpret_cast<const uint4*>(g_bin + (size_t)pBase * CAP);
        reinterpret_cast<uint4*>(&spts[0][0])[tid] = __ldcs(&src[tid]); // 64*CAP/2 = 512
    }
    __syncthreads();

    #pragma unroll
    for (int jj = 0; jj < 4; ++jj) {
        int pl = w * 4 + jj;                   // pixel-in-block 0..63
        int cnt = scnt[pl];
        float acc[8] = {0.f, 0.f, 0.f, 0.f, 0.f, 0.f, 0.f, 0.f};
        for (int t = 0; t < cnt; ++t) {
            uint2 v = spts[pl][t];             // smem broadcast
            int   pd  = (int)v.x;
            float na2 = __uint_as_float(v.y);

            float g[8];
            float s = 0.0f;
            #pragma unroll
            for (int m = 0; m < 8; ++m) {
                int d = lane + 32 * m;
                int k = d - pd - (d > pd);     // dup k=0 at d=pd,pd+1 (matches ref)
                float kf = (float)k;
                g[m] = ex2_fast(na2 * kf * kf);
                s = fmaf(g[m], g[m], s);
            }
            #pragma unroll
            for (int o = 16; o > 0; o >>= 1)
                s += __shfl_xor_sync(0xffffffffu, s, o);
            float inv = rsqrtf(s);             // s >= 1 (k=0 term), no eps clamp
            #pragma unroll
            for (int m = 0; m < 8; ++m)
                acc[m] = fmaf(g[m], inv, acc[m]);
        }
        // column pl: bank = (lane + pl) % 32 -> conflict-free
        #pragma unroll
        for (int m = 0; m < 8; ++m)
            tile[lane + 32 * m][pl] = acc[m];
    }
    __syncthreads();

    // transposed output: 16 warps x 16 depth rows, 64 consecutive pixels each
    // (two 128B warp-stores per row => 256B contiguous per block per row)
    #pragma unroll
    for (int m = 0; m < 16; ++m) {
        int d = w + m * 16;
        float* dst = out + (size_t)d * HW + pBase;
        int p0 = pBase + lane;
        if (p0 < HW)      __stcs(dst + lane,      tile[d][lane]);
        if (p0 + 32 < HW) __stcs(dst + lane + 32, tile[d][lane + 32]);
    }
}

// ---------------------------------------------------------------------------
// Launch
// ---------------------------------------------------------------------------
extern "C" void kernel_launch(void* const* d_in, const int* in_sizes, int n_in,
                              void* d_out, int out_size) {
    const int2*  pos   = (const int2*)d_in[0];   // [N,2] int32 (u=x, v=y)
    const int*   depth = (const int*)d_in[1];    // [N,1] int32
    const float* conf  = (const float*)d_in[2];  // [N,1] float32
    const int*   pW    = (const int*)d_in[4];    // feat_w scalar

    int npts = in_sizes[1];
    int HW   = out_size / DEPTH_DIM;

    const int SMEM = 66560 + 8192 + 256;         // ~75KB dynamic
    static bool attr_set = false;
    if (!attr_set) {
        cudaFuncSetAttribute(fused_kernel, cudaFuncAttributeMaxDynamicSharedMemorySize, SMEM);
        attr_set = true;
    }

    bin_kernel<<<(npts + 255) / 256, 256>>>(pos, depth, conf, pW, npts);
    fused_kernel<<<(HW + BLK_PIX - 1) / BLK_PIX, THREADS, SMEM>>>((float*)d_out, HW);
}